// round 12
// baseline (speedup 1.0000x reference)
#include <cuda_runtime.h>
#include <cstdint>

typedef unsigned long long u64;
typedef unsigned int u32;

#define G_DIM 2048
#define T_DIM 16
#define B_DIM 256
#define P_DIM 64

// Device-global scratch (no allocations allowed)
__device__ u64 g_pv[B_DIM];

// ---------------------------------------------------------------------------
// Ring ops in basis (1, w, w^2, w^3), w^4 = -1.
// ---------------------------------------------------------------------------
__device__ __forceinline__ void ringmul(int* z, const int* x, const int* y) {
    z[0] = x[0]*y[0] - x[1]*y[3] - x[2]*y[2] - x[3]*y[1];
    z[1] = x[0]*y[1] + x[1]*y[0] - x[2]*y[3] - x[3]*y[2];
    z[2] = x[0]*y[2] + x[1]*y[1] + x[2]*y[0] - x[3]*y[3];
    z[3] = x[0]*y[3] + x[1]*y[2] + x[2]*y[1] + x[3]*y[0];
}
__device__ __forceinline__ void ringcpy(int* d, const int* s) {
    d[0] = s[0]; d[1] = s[1]; d[2] = s[2]; d[3] = s[3];
}
__device__ __forceinline__ void ringpow(int* acc, const int* f, int n) {
    int base[4], tmp[4];
    acc[0] = 1; acc[1] = 0; acc[2] = 0; acc[3] = 0;
    ringcpy(base, f);
    while (n) {
        if (n & 1) { ringmul(tmp, acc, base); ringcpy(acc, tmp); }
        n >>= 1;
        if (n) { ringmul(tmp, base, base); ringcpy(base, tmp); }
    }
}
__device__ __forceinline__ int clamp_cnt(int c) {
    return c < 0 ? 0 : (c > T_DIM ? T_DIM : c);
}

// ---------------------------------------------------------------------------
// Init: pack param_vals (256 rows x 64 int32 0/1) into u64 bitsets.
// 8 blocks x 256 threads, 4 rows per warp, loads batched for MLP.
// ---------------------------------------------------------------------------
__global__ void pack_pv_kernel(const int* __restrict__ param_vals) {
    int warp = threadIdx.x >> 5, lane = threadIdx.x & 31;
    int row0 = (blockIdx.x * 8 + warp) * 4;
    int a[4], b[4];
    #pragma unroll
    for (int r = 0; r < 4; r++) {
        const int* p = param_vals + (size_t)(row0 + r) * P_DIM;
        a[r] = p[lane]; b[r] = p[lane + 32];
    }
    #pragma unroll
    for (int r = 0; r < 4; r++) {
        u32 lo = __ballot_sync(0xffffffffu, a[r] & 1);
        u32 hi = __ballot_sync(0xffffffffu, b[r] & 1);
        if (lane == 0) g_pv[row0 + r] = ((u64)hi << 32) | (u64)lo;
    }
}

// ---------------------------------------------------------------------------
// Main: 2048 blocks x 128 threads. Block = one g; thread handles b = tid and
// b = tid + 128 (term LDS amortized over both).
// Prologue (ONE barrier):
//   all 4 warps: ballot-pack 4 param rows each into s_term.{x,y}
//   warp 0: meta (s_pack, m0) + per-term pw -> s_term[t].z
//   warp kk (1..3): m_kk via ballot; lane b<=m computes the row entry
//                   (1+w^kk)^(m-b) (1-w^kk)^b via square-and-multiply ringpow
//                   (pure compute -- no dependent table load).
// Compute: branch-free packed-byte-counter parity (2 chains per b),
//          3 smem row lookups + 2 ring muls per b, scale, float4 store.
// Output float32 (B, G, 4) in reference basis (1,w,w^2,w^7): c3 = -z3.
// ---------------------------------------------------------------------------
__global__ void __launch_bounds__(128, 12)
nodephases_main_kernel(const int* __restrict__ params,
                       const int* __restrict__ phases,
                       const int* __restrict__ counts,
                       float* __restrict__ out) {
    const int g    = blockIdx.x;
    const int tid  = threadIdx.x;
    const int lane = tid & 31;
    const int warp = tid >> 5;

    __shared__ int4 s_term[T_DIM];     // x=lo, y=hi, z=pw
    __shared__ int4 s_rows[3][17];     // row entries per class (k -> [k-1])
    __shared__ int2 s_meta;            // x=s_pack, y=m0

    // ---- issue small loads first (role work depends on them) ----
    int c = clamp_cnt(counts[g]);
    int p = (lane < 16) ? (phases[g * T_DIM + lane] & 7) : 0;

    // ---- pack: each warp 4 rows, loads batched for MLP ----
    {
        const int* basep = params + (size_t)g * (T_DIM * P_DIM) + warp * 4 * P_DIM;
        int a[4], b[4];
        #pragma unroll
        for (int r = 0; r < 4; r++) {
            a[r] = basep[r * P_DIM + lane];
            b[r] = basep[r * P_DIM + 32 + lane];
        }

        // ---- role work (overlaps the params loads above) ----
        u32 vm = (c >= 16) ? 0xFFFFu : ((1u << c) - 1u);
        if (warp == 0) {
            int k  = p & 3;
            int sg = (p >> 2) & 1;
            u32 b0m = __ballot_sync(0xffffffffu, k == 0) & vm;
            u32 b1m = __ballot_sync(0xffffffffu, k == 1) & vm;
            u32 b2m = __ballot_sync(0xffffffffu, k == 2) & vm;
            u32 b3m = __ballot_sync(0xffffffffu, k == 3) & vm;
            u32 sgm = __ballot_sync(0xffffffffu, sg == 1) & vm;
            if (lane < 16) {
                int valid = (vm >> lane) & 1;
                s_term[lane].z = valid ? (sg ? -(1 << (8 * k)) : (1 << (8 * k))) : 0;
            }
            if (lane == 0) {
                int s0 = __popc(b0m & sgm), s1 = __popc(b1m & sgm),
                    s2 = __popc(b2m & sgm), s3 = __popc(b3m & sgm);
                s_meta = make_int2(s0 | (s1 << 8) | (s2 << 16) | (s3 << 24),
                                   __popc(b0m));
            }
        } else {
            const int kk = warp;            // class 1..3
            u32 km = __ballot_sync(0xffffffffu, ((p & 3) == kk) && (lane < 16)) & vm;
            int m = __popc(km);
            if (lane <= m) {                // entry b = lane: (1+w)^{m-b} (1-w)^b
                int fp[4] = {1, 0, 0, 0}; fp[kk] = 1;
                int fm[4] = {1, 0, 0, 0}; fm[kk] = -1;
                int pa[4], pb[4], acc[4];
                ringpow(pa, fp, m - lane);
                ringpow(pb, fm, lane);
                ringmul(acc, pa, pb);
                s_rows[kk - 1][lane] = make_int4(acc[0], acc[1], acc[2], acc[3]);
            }
        }

        // ---- pack ballots (params loads have landed by now) ----
        #pragma unroll
        for (int r = 0; r < 4; r++) {
            u32 lo = __ballot_sync(0xffffffffu, a[r] & 1);
            u32 hi = __ballot_sync(0xffffffffu, b[r] & 1);
            if (lane == 0) {
                s_term[warp * 4 + r].x = (int)lo;
                s_term[warp * 4 + r].y = (int)hi;
            }
        }
    }
    __syncthreads();

    // ---- compute: 2 b's per thread, terms shared ----
    const u64 va = g_pv[tid];
    const u64 vb = g_pv[tid + 128];
    const u32 va_lo = (u32)va, va_hi = (u32)(va >> 32);
    const u32 vb_lo = (u32)vb, vb_hi = (u32)(vb >> 32);

    const int2 meta = s_meta;

    int cpA0 = meta.x, cpB0 = 0x10101010;
    int cpA1 = meta.x, cpB1 = 0x10101010;

    #pragma unroll
    for (int t = 0; t < 8; t++) {
        int4 tw = s_term[t];
        u32 x0 = ((u32)tw.x & va_lo) ^ ((u32)tw.y & va_hi);
        u32 x1 = ((u32)tw.x & vb_lo) ^ ((u32)tw.y & vb_hi);
        cpA0 += (int)(__popc(x0) & 1u) * tw.z;
        cpA1 += (int)(__popc(x1) & 1u) * tw.z;
    }
    #pragma unroll
    for (int t = 8; t < 16; t++) {
        int4 tw = s_term[t];
        u32 x0 = ((u32)tw.x & va_lo) ^ ((u32)tw.y & va_hi);
        u32 x1 = ((u32)tw.x & vb_lo) ^ ((u32)tw.y & vb_hi);
        cpB0 += (int)(__popc(x0) & 1u) * tw.z;
        cpB1 += (int)(__popc(x1) & 1u) * tw.z;
    }

    const int cp[2] = { cpA0 + cpB0 - 0x10101010, cpA1 + cpB1 - 0x10101010 };
    const int bb[2] = { tid, tid + 128 };

    #pragma unroll
    for (int j = 0; j < 2; j++) {
        int b0 = cp[j] & 255;
        int b1 = (cp[j] >> 8) & 255;
        int b2 = (cp[j] >> 16) & 255;
        int b3 = (cp[j] >> 24) & 255;

        int4 A = s_rows[0][b1];
        int4 B = s_rows[1][b2];
        int4 C = s_rows[2][b3];

        int r0 = A.x*B.x - A.y*B.w - A.z*B.z - A.w*B.y;
        int r1 = A.x*B.y + A.y*B.x - A.z*B.w - A.w*B.z;
        int r2 = A.x*B.z + A.y*B.y + A.z*B.x - A.w*B.w;
        int r3 = A.x*B.w + A.y*B.z + A.z*B.y + A.w*B.x;

        int z0 = r0*C.x - r1*C.w - r2*C.z - r3*C.y;
        int z1 = r0*C.y + r1*C.x - r2*C.w - r3*C.z;
        int z2 = r0*C.z + r1*C.y + r2*C.x - r3*C.w;
        int z3 = r0*C.w + r1*C.z + r2*C.y + r3*C.x;

        int sc = (b0 == 0) ? (1 << meta.y) : 0;

        float4* o = (float4*)out + (size_t)bb[j] * G_DIM + g;
        *o = make_float4((float)(z0 * sc), (float)(z1 * sc),
                         (float)(z2 * sc), (float)(-z3 * sc));
    }
}

// ---------------------------------------------------------------------------
// Launch. Inputs identified BY SIZE (ordering-proof):
//   phases 32768 | params 2097152 | counts 2048 | param_vals 16384 | opp 32
// ---------------------------------------------------------------------------
extern "C" void kernel_launch(void* const* d_in, const int* in_sizes, int n_in,
                              void* d_out, int out_size) {
    const int* phases = nullptr;
    const int* params = nullptr;
    const int* counts = nullptr;
    const int* param_vals = nullptr;

    for (int i = 0; i < n_in; i++) {
        switch (in_sizes[i]) {
            case G_DIM * T_DIM:         phases     = (const int*)d_in[i]; break;
            case G_DIM * T_DIM * P_DIM: params     = (const int*)d_in[i]; break;
            case G_DIM:                 counts     = (const int*)d_in[i]; break;
            case B_DIM * P_DIM:         param_vals = (const int*)d_in[i]; break;
            default: break;  // one_plus_phases (32 floats) — unused
        }
    }

    pack_pv_kernel<<<8, 256>>>(param_vals);
    nodephases_main_kernel<<<G_DIM, 128>>>(params, phases, counts, (float*)d_out);
}